// round 14
// baseline (speedup 1.0000x reference)
#include <cuda_runtime.h>
#include <math.h>

#define H 2048
#define S 2048
#define V 50257
#define RCH 16
#define NB_LSE 64

// Scratch (device globals — no allocation allowed)
__device__ float g_emb[H];
__device__ float g_part[RCH * H];
__device__ float g_x[H];
__device__ float g_gx[3 * H];
__device__ float g_gh[3 * H];
__device__ float g_hnew[H];
__device__ float g_pmax[NB_LSE];
__device__ float g_psum[NB_LSE];
// sync state (all zero-initialized; every kernel resets its own before exit)
__device__ int g_ac_count;   // k_AC: colsum+misc completion
__device__ int g_ac_done;    // k_AC: block completion (for reset)
__device__ int g_gru_flag;   // k_out: GRU completion
__device__ int g_out_done;   // k_out: block completion (for reset)
__device__ int g_count;      // k_lsesub barrier
__device__ volatile int g_release;

__device__ __forceinline__ float warp_reduce(float v) {
    #pragma unroll
    for (int o = 16; o > 0; o >>= 1) v += __shfl_xor_sync(0xFFFFFFFFu, v, o);
    return v;
}

// Two-row warp dot over H floats (512 float4), 4 phases of 8 in-flight LDG.128.
__device__ __forceinline__ void dot2(const float4* __restrict__ w0,
                                     const float4* __restrict__ w1,
                                     const float4* __restrict__ sx,
                                     int lane, float& acc0, float& acc1) {
    #pragma unroll
    for (int p = 0; p < 4; p++) {
        float4 a0[4], a1[4];
        #pragma unroll
        for (int b = 0; b < 4; b++) a0[b] = __ldcs(&w0[lane + 32 * (4 * p + b)]);
        #pragma unroll
        for (int b = 0; b < 4; b++) a1[b] = __ldcs(&w1[lane + 32 * (4 * p + b)]);
        #pragma unroll
        for (int b = 0; b < 4; b++) {
            float4 xv = sx[lane + 32 * (4 * p + b)];
            acc0 = fmaf(a0[b].x, xv.x, acc0); acc0 = fmaf(a0[b].y, xv.y, acc0);
            acc0 = fmaf(a0[b].z, xv.z, acc0); acc0 = fmaf(a0[b].w, xv.w, acc0);
            acc1 = fmaf(a1[b].x, xv.x, acc1); acc1 = fmaf(a1[b].y, xv.y, acc1);
            acc1 = fmaf(a1[b].z, xv.z, acc1); acc1 = fmaf(a1[b].w, xv.w, acc1);
        }
    }
}

// gh block body: 16 rows of w_hh (2/warp) against h0 staged in smem
__device__ __forceinline__ void gh_block(const float* __restrict__ w_hh,
                                         const float* __restrict__ b_hh,
                                         const float* __restrict__ h0,
                                         float4* sx, int row_base) {
    const float4* x4 = (const float4*)h0;
    sx[threadIdx.x] = x4[threadIdx.x];
    sx[threadIdx.x + 256] = x4[threadIdx.x + 256];
    __syncthreads();
    int w = threadIdx.x >> 5, lane = threadIdx.x & 31;
    int r0 = row_base + w * 2;
    const float4* w0 = (const float4*)(w_hh + (size_t)r0 * H);
    float acc0 = 0.f, acc1 = 0.f;
    dot2(w0, w0 + H / 4, sx, lane, acc0, acc1);
    acc0 = warp_reduce(acc0);
    acc1 = warp_reduce(acc1);
    if (lane == 0) {
        g_gh[r0]     = acc0 + b_hh[r0];
        g_gh[r0 + 1] = acc1 + b_hh[r0 + 1];
    }
}

__device__ __forceinline__ void spin_until(int* flag, int target) {
    if (threadIdx.x == 0) {
        while (*((volatile int*)flag) < target) { __nanosleep(64); }
    }
    __syncthreads();
    __threadfence();
}

// ---------------------------------------------------------------------------
// K_AC (merged k_A + k_comb): colsum partials (128) | misc (8) |
// comb matvec (128, waits on flag) | gh rows 0..4095 (256)
#define CS_BLOCKS 128
#define MISC_BLOCKS 8
#define PRE_BLOCKS (CS_BLOCKS + MISC_BLOCKS)     // 136
#define COMB_BLOCKS 128
#define GH_AC 256
#define AC_GRID (PRE_BLOCKS + COMB_BLOCKS + GH_AC)  // 520
__global__ __launch_bounds__(256, 3) void k_AC(const float* __restrict__ enc,
                                               const int* __restrict__ input_id,
                                               const float* __restrict__ emb,
                                               float* __restrict__ out_attn,
                                               const float* __restrict__ comb_w,
                                               const float* __restrict__ comb_b,
                                               const float* __restrict__ w_hh,
                                               const float* __restrict__ b_hh,
                                               const float* __restrict__ h0) {
    __shared__ float4 sbuf[2 * (H / 4)];
    int b = blockIdx.x;
    int t = threadIdx.x;
    if (b < CS_BLOCKS) {
        int chunk = b >> 3;                      // 0..15
        int col = (b & 7) * 256 + t;
        int r0 = chunk * (S / RCH);
        float s = 0.f;
        #pragma unroll 8
        for (int r = 0; r < S / RCH; ++r)
            s += __ldcs(&enc[(size_t)(r0 + r) * H + col]);
        g_part[chunk * H + col] = s;
        __syncthreads();
        __threadfence();
        if (t == 0) atomicAdd(&g_ac_count, 1);
    } else if (b < PRE_BLOCKS) {
        int i = (b - CS_BLOCKS) * 256 + t;       // 0..2047
        g_emb[i] = emb[(size_t)(*input_id) * H + i];
        out_attn[i] = 1.0f;
        __syncthreads();
        __threadfence();
        if (t == 0) atomicAdd(&g_ac_count, 1);
    } else if (b < PRE_BLOCKS + COMB_BLOCKS) {
        spin_until(&g_ac_count, PRE_BLOCKS);
        float4* se = sbuf;
        float4* sc = sbuf + H / 4;
        const float4* e4 = (const float4*)g_emb;
        se[t] = e4[t];
        se[t + 256] = e4[t + 256];
        const float4* p4 = (const float4*)g_part;
        #pragma unroll
        for (int half = 0; half < 2; half++) {
            int idx = t + 256 * half;
            float4 s = {0.f, 0.f, 0.f, 0.f};
            #pragma unroll
            for (int c = 0; c < RCH; ++c) {
                float4 v = p4[c * (H / 4) + idx];
                s.x += v.x; s.y += v.y; s.z += v.z; s.w += v.w;
            }
            sc[idx] = s;
        }
        __syncthreads();
        int w = t >> 5, lane = t & 31;
        int r0 = (b - PRE_BLOCKS) * 16 + w * 2;  // 0..2046
        const float4* w0 = (const float4*)(comb_w + (size_t)r0 * 2 * H);
        const float4* w1 = w0 + 2 * H / 4;
        float acc0 = 0.f, acc1 = 0.f;
        dot2(w0, w1, se, lane, acc0, acc1);                    // emb half
        dot2(w0 + H / 4, w1 + H / 4, sc, lane, acc0, acc1);    // colsum half
        acc0 = warp_reduce(acc0);
        acc1 = warp_reduce(acc1);
        if (lane == 0) {
            g_x[r0]     = fmaxf(acc0 + comb_b[r0], 0.f);
            g_x[r0 + 1] = fmaxf(acc1 + comb_b[r0 + 1], 0.f);
        }
    } else {
        gh_block(w_hh, b_hh, h0, sbuf, (b - PRE_BLOCKS - COMB_BLOCKS) * 16);
    }
    // reset sync state (replay-safe): last block to finish zeroes flags
    __syncthreads();
    if (t == 0) {
        __threadfence();
        int c = atomicAdd(&g_ac_done, 1);
        if (c == AC_GRID - 1) {
            g_ac_done = 0;
            g_ac_count = 0;
            __threadfence();
        }
    }
}

// K_D: gx = w_ih @ relu_x + b_ih (384 blocks) | gh rows 4096..6143 (128 blocks)
#define GX_BLOCKS 384
#define GH_D 128
__global__ __launch_bounds__(256, 3) void k_gates_ih(const float* __restrict__ w_ih,
                                                     const float* __restrict__ b_ih,
                                                     const float* __restrict__ w_hh,
                                                     const float* __restrict__ b_hh,
                                                     const float* __restrict__ h0) {
    __shared__ float4 sx[H / 4];
    int b = blockIdx.x;
    if (b < GX_BLOCKS) {
        const float4* x4 = (const float4*)g_x;
        sx[threadIdx.x] = x4[threadIdx.x];
        sx[threadIdx.x + 256] = x4[threadIdx.x + 256];
        __syncthreads();
        int w = threadIdx.x >> 5, lane = threadIdx.x & 31;
        int r0 = b * 16 + w * 2;                 // 0..6142
        const float4* w0 = (const float4*)(w_ih + (size_t)r0 * H);
        float acc0 = 0.f, acc1 = 0.f;
        dot2(w0, w0 + H / 4, sx, lane, acc0, acc1);
        acc0 = warp_reduce(acc0);
        acc1 = warp_reduce(acc1);
        if (lane == 0) {
            g_gx[r0]     = acc0 + b_ih[r0];
            g_gx[r0 + 1] = acc1 + b_ih[r0 + 1];
        }
    } else {
        gh_block(w_hh, b_hh, h0, sx, 4096 + (b - GX_BLOCKS) * 16);
    }
}

// K_F (merged k_gru + k_out): blocks 0..7 compute GRU -> g_hnew + out_h, set
// flag; row blocks wait for flag then stream out_w. Replay-safe reset at end.
#define GRU_BLOCKS 8
#define ROW_BLOCKS ((V + 15) / 16)               // 3142
#define OUT_GRID (GRU_BLOCKS + ROW_BLOCKS)       // 3150
__global__ __launch_bounds__(256, 4) void k_out(const float* __restrict__ out_w,
                                                const float* __restrict__ out_b,
                                                const float* __restrict__ h0,
                                                float* __restrict__ out_h,
                                                float* __restrict__ out) {
    __shared__ float4 sx[H / 4];
    int b = blockIdx.x;
    int t = threadIdx.x;
    if (b < GRU_BLOCKS) {
        int i = b * 256 + t;                     // 0..2047
        float r = 1.f / (1.f + __expf(-(g_gx[i]         + g_gh[i])));
        float z = 1.f / (1.f + __expf(-(g_gx[H + i]     + g_gh[H + i])));
        float n = tanhf(g_gx[2 * H + i] + r * g_gh[2 * H + i]);
        float hn = (1.f - z) * n + z * h0[i];
        g_hnew[i] = hn;
        out_h[i]  = hn;
        __syncthreads();
        __threadfence();
        if (t == 0) atomicAdd(&g_gru_flag, 1);
    } else {
        spin_until(&g_gru_flag, GRU_BLOCKS);
        const float4* x4 = (const float4*)g_hnew;
        sx[t] = x4[t];
        sx[t + 256] = x4[t + 256];
        __syncthreads();
        int w = t >> 5, lane = t & 31;
        int r0 = (b - GRU_BLOCKS) * 16 + w * 2;
        if (r0 < V) {
            const float4* w0 = (const float4*)(out_w + (size_t)r0 * H);
            float acc0 = 0.f, acc1 = 0.f;
            if (r0 + 1 < V) {
                dot2(w0, w0 + H / 4, sx, lane, acc0, acc1);
            } else {
                dot2(w0, w0, sx, lane, acc0, acc1);  // dup row; acc1 unused
            }
            acc0 = warp_reduce(acc0);
            acc1 = warp_reduce(acc1);
            if (lane == 0) {
                out[r0] = acc0 + out_b[r0];
                if (r0 + 1 < V) out[r0 + 1] = acc1 + out_b[r0 + 1];
            }
        }
    }
    __syncthreads();
    if (t == 0) {
        __threadfence();
        int c = atomicAdd(&g_out_done, 1);
        if (c == OUT_GRID - 1) {
            g_out_done = 0;
            g_gru_flag = 0;
            __threadfence();
        }
    }
}

// K_G: fused log-softmax normalize. 64 blocks, logits held in registers
// across a global spin barrier (64 blocks are always co-resident).
__global__ __launch_bounds__(256) void k_lsesub(float* __restrict__ out) {
    __shared__ float sm[256];
    __shared__ float s_lse;
    int t = threadIdx.x;
    int gtid = blockIdx.x * 256 + t;
    float v[4];
    float m = -INFINITY;
    #pragma unroll
    for (int k = 0; k < 4; k++) {
        int i = gtid + k * (NB_LSE * 256);
        v[k] = (i < V) ? out[i] : -INFINITY;
        m = fmaxf(m, v[k]);
    }
    sm[t] = m; __syncthreads();
    #pragma unroll
    for (int s = 128; s > 0; s >>= 1) {
        if (t < s) sm[t] = fmaxf(sm[t], sm[t + s]);
        __syncthreads();
    }
    float bmax = sm[0]; __syncthreads();
    float sum = 0.f;
    #pragma unroll
    for (int k = 0; k < 4; k++)
        sum += (v[k] > -INFINITY) ? __expf(v[k] - bmax) : 0.f;
    sm[t] = sum; __syncthreads();
    #pragma unroll
    for (int s = 128; s > 0; s >>= 1) {
        if (t < s) sm[t] += sm[t + s];
        __syncthreads();
    }
    if (t == 0) { g_pmax[blockIdx.x] = bmax; g_psum[blockIdx.x] = sm[0]; }
    __threadfence();
    __syncthreads();
    if (t == 0) {
        int my = g_release;
        int c = atomicAdd(&g_count, 1);
        if (c == NB_LSE - 1) {
            g_count = 0;
            __threadfence();
            atomicAdd((int*)&g_release, 1);
        } else {
            while (g_release == my) { __nanosleep(64); }
        }
        __threadfence();
        float M = -INFINITY;
        for (int i = 0; i < NB_LSE; i++) M = fmaxf(M, g_pmax[i]);
        float ssum = 0.f;
        for (int i = 0; i < NB_LSE; i++) ssum += g_psum[i] * __expf(g_pmax[i] - M);
        s_lse = M + logf(ssum);
    }
    __syncthreads();
    float lse = s_lse;
    #pragma unroll
    for (int k = 0; k < 4; k++) {
        int i = gtid + k * (NB_LSE * 256);
        if (i < V) out[i] = v[k] - lse;
    }
}

// ---------------------------------------------------------------------------
extern "C" void kernel_launch(void* const* d_in, const int* in_sizes, int n_in,
                              void* d_out, int out_size) {
    const int*   input_id = (const int*)  d_in[0];
    const float* hidden   = (const float*)d_in[1];
    const float* enc      = (const float*)d_in[2];
    const float* emb      = (const float*)d_in[3];
    // d_in[4], d_in[5]: attn linear — dead (softmax over singleton)
    const float* comb_w   = (const float*)d_in[6];
    const float* comb_b   = (const float*)d_in[7];
    const float* w_ih     = (const float*)d_in[8];
    const float* w_hh     = (const float*)d_in[9];
    const float* b_ih     = (const float*)d_in[10];
    const float* b_hh     = (const float*)d_in[11];
    const float* out_w    = (const float*)d_in[12];
    const float* out_b    = (const float*)d_in[13];
    float* out = (float*)d_out; // [log_probs(V) | h_new(H) | attn_weights(S)]

    k_AC<<<AC_GRID, 256>>>(enc, input_id, emb, out + V + H,
                           comb_w, comb_b, w_hh, b_hh, hidden);
    k_gates_ih<<<GX_BLOCKS + GH_D, 256>>>(w_ih, b_ih, w_hh, b_hh, hidden);
    k_out<<<OUT_GRID, 256>>>(out_w, out_b, hidden, out + V, out);
    k_lsesub<<<NB_LSE, 256>>>(out);
}